// round 5
// baseline (speedup 1.0000x reference)
#include <cuda_runtime.h>
#include <math.h>

#define HIDDEN 128
#define MIX 8
#define MAXN 10000
#define MAXE 512000

// Scratch (allocation-free rule: __device__ globals)
__device__ __align__(16) float g_T[MAXN * MIX];      // per-node hyper weights
__device__ int g_count[MAXN];
__device__ int g_cursor[MAXN];
__device__ int g_offsets[MAXN + 1];
__device__ __align__(8) int2 g_se[MAXE];             // sorted (src, edge_id)
__device__ __align__(8) int2 g_sd[MAXE];             // decoded (src, dst) staging
__device__ int g_is64;

__device__ __forceinline__ float gelu_exact(float x) {
    return 0.5f * x * (1.0f + erff(x * 0.70710678118654752f));
}

// ---- packed f32x2 helpers (sm_103a) ----
__device__ __forceinline__ unsigned long long f2_pack(float lo, float hi) {
    unsigned long long r;
    asm("mov.b64 %0, {%1, %2};" : "=l"(r) : "f"(lo), "f"(hi));
    return r;
}
__device__ __forceinline__ void f2_unpack(unsigned long long v, float& lo, float& hi) {
    asm("mov.b64 {%0, %1}, %2;" : "=f"(lo), "=f"(hi) : "l"(v));
}
__device__ __forceinline__ unsigned long long f2_fma(unsigned long long a,
                                                     unsigned long long b,
                                                     unsigned long long c) {
    unsigned long long r;
    asm("fma.rn.f32x2 %0, %1, %2, %3;" : "=l"(r) : "l"(a), "l"(b), "l"(c));
    return r;
}

__device__ __forceinline__ void load_edge(const void* ei, int e, int E, int& s, int& d) {
    if (g_is64) {
        const long long* p = (const long long*)ei;
        s = (int)p[e];
        d = (int)p[(size_t)E + e];
    } else {
        const int* p = (const int*)ei;
        s = p[e];
        d = p[(size_t)E + e];
    }
}

// Zero counters + detect int64-vs-int32 edge_index (node ids < N => int64 high words 0)
__global__ void prep_kernel(const unsigned int* __restrict__ w, int N) {
    int i = blockIdx.x * blockDim.x + threadIdx.x;
    if (i < N) { g_count[i] = 0; g_cursor[i] = 0; }
    if (i == 0) {
        int is64 = 1;
        #pragma unroll
        for (int k = 0; k < 64; k++)
            if (w[2 * k + 1] != 0u) is64 = 0;
        g_is64 = is64;
    }
}

// Decode edges once, stage (src,dst), build dst histogram.
__global__ void hist_kernel(const void* __restrict__ ei, int E) {
    int e = blockIdx.x * blockDim.x + threadIdx.x;
    if (e >= E) return;
    int s, d;
    load_edge(ei, e, E, s, d);
    g_sd[e] = make_int2(s, d);
    atomicAdd(&g_count[d], 1);
}

#define SCAN_T 1024
__global__ void scan_kernel(int N) {
    __shared__ int wsum[32];
    int t = threadIdx.x;
    int lane = t & 31, wid = t >> 5;
    int per = (N + SCAN_T - 1) / SCAN_T;
    int beg = t * per;
    int end = min(beg + per, N);

    int local = 0;
    for (int i = beg; i < end; i++) local += g_count[i];

    int v = local;
    #pragma unroll
    for (int off = 1; off < 32; off <<= 1) {
        int u = __shfl_up_sync(0xffffffffu, v, off);
        if (lane >= off) v += u;
    }
    if (lane == 31) wsum[wid] = v;
    __syncthreads();
    if (wid == 0) {
        int wv = wsum[lane];
        #pragma unroll
        for (int off = 1; off < 32; off <<= 1) {
            int u = __shfl_up_sync(0xffffffffu, wv, off);
            if (lane >= off) wv += u;
        }
        wsum[lane] = wv;
    }
    __syncthreads();

    int warp_excl = (wid == 0) ? 0 : wsum[wid - 1];
    int run = warp_excl + (v - local);
    for (int i = beg; i < end; i++) { g_offsets[i] = run; run += g_count[i]; }
    if (t == SCAN_T - 1) g_offsets[N] = run;
}

__global__ void reorder_kernel(int E) {
    int e = blockIdx.x * blockDim.x + threadIdx.x;
    if (e >= E) return;
    int2 sd = g_sd[e];
    int pos = g_offsets[sd.y] + atomicAdd(&g_cursor[sd.y], 1);
    g_se[pos] = make_int2(sd.x, e);
}

// T[n,m] = dot( gelu( X[n,:] @ W_A^T ), W_B[m,:] )
__global__ void compute_T_kernel(const float* __restrict__ X,
                                 const float* __restrict__ WA,
                                 const float* __restrict__ WB,
                                 int N) {
    __shared__ float xs[16][HIDDEN];
    __shared__ float gs[16][HIDDEN];
    int t = threadIdx.x;
    int base = blockIdx.x * 16;

    #pragma unroll
    for (int r = 0; r < 16; r++) {
        int n = base + r;
        xs[r][t] = (n < N) ? X[(size_t)n * HIDDEN + t] : 0.f;
    }
    __syncthreads();

    const float* wa = WA + (size_t)t * HIDDEN;
    float acc[16];
    #pragma unroll
    for (int r = 0; r < 16; r++) acc[r] = 0.f;
    for (int k = 0; k < HIDDEN; k++) {
        float w = __ldg(wa + k);
        #pragma unroll
        for (int r = 0; r < 16; r++) acc[r] += xs[r][k] * w;
    }
    #pragma unroll
    for (int r = 0; r < 16; r++) gs[r][t] = gelu_exact(acc[r]);
    __syncthreads();

    int r = t >> 3, m = t & 7;
    int n = base + r;
    if (n < N) {
        const float* wb = WB + (size_t)m * HIDDEN;
        float a = 0.f;
        for (int k = 0; k < HIDDEN; k++) a += gs[r][k] * __ldg(wb + k);
        g_T[(size_t)n * MIX + m] = a;
    }
}

// ONE WARP per dst node. Lane l owns h = 4l..4l+3. Mix dim packed into 4 f32x2 pairs.
// T row (32B) loads directly as 2x ulonglong2 -> pair layout is free.
// Per edge per thread: Phase A = 16 FFMA2 (+4 dup-packs, ALU pipe), Phase C = 16 FFMA2.
#define WPB 8
__global__ void __launch_bounds__(32 * WPB, 3)
fused_kernel(const float* __restrict__ X, float* __restrict__ out, int N) {
    int d = blockIdx.x * WPB + (threadIdx.x >> 5);
    if (d >= N) return;
    int lane = threadIdx.x & 31;

    int beg = g_offsets[d];
    int end = g_offsets[d + 1];
    if (beg == end) return;

    // acc[c][j]: h-component c (of the float4), m-pair j: (m=2j, m=2j+1)
    unsigned long long acc[4][4];
    #pragma unroll
    for (int c = 0; c < 4; c++)
        #pragma unroll
        for (int j = 0; j < 4; j++) acc[c][j] = 0ull;

    // Phase A: agg[d, 4l+c, 2j:2j+2] += X[s, 4l+c] * T[s, 2j:2j+2]
    for (int i = beg; i < end; i++) {
        int s = __ldg(&g_se[i].x);
        float4 x = __ldg((const float4*)(X + (size_t)s * HIDDEN) + lane);
        const ulonglong2* Tp = (const ulonglong2*)(g_T + (size_t)s * MIX);
        ulonglong2 ta = __ldg(Tp);
        ulonglong2 tb = __ldg(Tp + 1);
        unsigned long long tp0 = ta.x, tp1 = ta.y, tp2 = tb.x, tp3 = tb.y;
        unsigned long long dx[4] = {
            f2_pack(x.x, x.x), f2_pack(x.y, x.y),
            f2_pack(x.z, x.z), f2_pack(x.w, x.w)
        };
        #pragma unroll
        for (int c = 0; c < 4; c++) {
            acc[c][0] = f2_fma(dx[c], tp0, acc[c][0]);
            acc[c][1] = f2_fma(dx[c], tp1, acc[c][1]);
            acc[c][2] = f2_fma(dx[c], tp2, acc[c][2]);
            acc[c][3] = f2_fma(dx[c], tp3, acc[c][3]);
        }
    }

    // Phase B: gelu in registers
    #pragma unroll
    for (int c = 0; c < 4; c++)
        #pragma unroll
        for (int j = 0; j < 4; j++) {
            float lo, hi;
            f2_unpack(acc[c][j], lo, hi);
            acc[c][j] = f2_pack(gelu_exact(lo), gelu_exact(hi));
        }

    // Phase C: out[e, 4l+c] = sum_j dot2(acc[c][j], T[s_e, 2j:2j+2])
    for (int i = beg; i < end; i++) {
        int2 p = __ldg(&g_se[i]);
        const ulonglong2* Tp = (const ulonglong2*)(g_T + (size_t)p.x * MIX);
        ulonglong2 ta = __ldg(Tp);
        ulonglong2 tb = __ldg(Tp + 1);
        unsigned long long tp0 = ta.x, tp1 = ta.y, tp2 = tb.x, tp3 = tb.y;
        float4 o;
        #pragma unroll
        for (int c = 0; c < 4; c++) {
            unsigned long long r = f2_fma(acc[c][0], tp0, 0ull);
            r = f2_fma(acc[c][1], tp1, r);
            r = f2_fma(acc[c][2], tp2, r);
            r = f2_fma(acc[c][3], tp3, r);
            float lo, hi;
            f2_unpack(r, lo, hi);
            ((float*)&o)[c] = lo + hi;
        }
        *(float4*)(out + (size_t)p.y * HIDDEN + 4 * lane) = o;
    }
}

// Optional tail: src/dst appended as floats (full-tuple output case)
__global__ void tail_kernel(float* __restrict__ out, int E) {
    int e = blockIdx.x * blockDim.x + threadIdx.x;
    if (e >= E) return;
    int2 sd = g_sd[e];
    out[(size_t)E * HIDDEN + e] = (float)sd.x;
    out[(size_t)E * HIDDEN + E + e] = (float)sd.y;
}

extern "C" void kernel_launch(void* const* d_in, const int* in_sizes, int n_in,
                              void* d_out, int out_size) {
    const float* X  = (const float*)d_in[0];
    const float* WA = (const float*)d_in[1];
    const float* WB = (const float*)d_in[2];
    const void*  ei = d_in[3];

    int N = in_sizes[0] / HIDDEN;   // 10000
    int E = in_sizes[3] / 2;        // 320000
    float* out = (float*)d_out;

    prep_kernel<<<(N + 255) / 256, 256>>>((const unsigned int*)ei, N);
    hist_kernel<<<(E + 255) / 256, 256>>>(ei, E);
    scan_kernel<<<1, SCAN_T>>>(N);
    reorder_kernel<<<(E + 255) / 256, 256>>>(E);
    compute_T_kernel<<<(N + 15) / 16, 128>>>(X, WA, WB, N);
    fused_kernel<<<(N + WPB - 1) / WPB, 32 * WPB>>>(X, out, N);

    if ((long long)out_size >= (long long)E * (HIDDEN + 2)) {
        tail_kernel<<<(E + 255) / 256, 256>>>(out, E);
    }
}

// round 6
// speedup vs baseline: 1.6221x; 1.6221x over previous
#include <cuda_runtime.h>
#include <math.h>

#define HIDDEN 128
#define MIX 8
#define MAXN 10000
#define MAXE 512000

// Scratch (allocation-free rule: __device__ globals)
__device__ __align__(16) float g_T[MAXN * MIX];      // per-node hyper weights
__device__ int g_count[MAXN];
__device__ int g_cursor[MAXN];
__device__ int g_offsets[MAXN + 1];
__device__ __align__(8) int2 g_se[MAXE];             // sorted (src, edge_id)
__device__ int g_is64;

__device__ __forceinline__ float gelu_exact(float x) {
    return 0.5f * x * (1.0f + erff(x * 0.70710678118654752f));
}

__device__ __forceinline__ void load_edge(const void* ei, int e, int E, int& s, int& d) {
    if (g_is64) {
        const long long* p = (const long long*)ei;
        s = (int)p[e];
        d = (int)p[(size_t)E + e];
    } else {
        const int* p = (const int*)ei;
        s = p[e];
        d = p[(size_t)E + e];
    }
}

// Zero counters + detect int64-vs-int32 edge_index (node ids < N => int64 high words 0)
__global__ void prep_kernel(const unsigned int* __restrict__ w, int N) {
    int i = blockIdx.x * blockDim.x + threadIdx.x;
    if (i < N) { g_count[i] = 0; g_cursor[i] = 0; }
    if (i == 0) {
        int is64 = 1;
        #pragma unroll
        for (int k = 0; k < 64; k++)
            if (w[2 * k + 1] != 0u) is64 = 0;
        g_is64 = is64;
    }
}

__global__ void hist_kernel(const void* __restrict__ ei, int E) {
    int e = blockIdx.x * blockDim.x + threadIdx.x;
    if (e >= E) return;
    int s, d;
    load_edge(ei, e, E, s, d);
    atomicAdd(&g_count[d], 1);
}

#define SCAN_T 1024
__global__ void scan_kernel(int N) {
    __shared__ int wsum[32];
    int t = threadIdx.x;
    int lane = t & 31, wid = t >> 5;
    int per = (N + SCAN_T - 1) / SCAN_T;
    int beg = t * per;
    int end = min(beg + per, N);

    int local = 0;
    for (int i = beg; i < end; i++) local += g_count[i];

    int v = local;
    #pragma unroll
    for (int off = 1; off < 32; off <<= 1) {
        int u = __shfl_up_sync(0xffffffffu, v, off);
        if (lane >= off) v += u;
    }
    if (lane == 31) wsum[wid] = v;
    __syncthreads();
    if (wid == 0) {
        int wv = wsum[lane];
        #pragma unroll
        for (int off = 1; off < 32; off <<= 1) {
            int u = __shfl_up_sync(0xffffffffu, wv, off);
            if (lane >= off) wv += u;
        }
        wsum[lane] = wv;
    }
    __syncthreads();

    int warp_excl = (wid == 0) ? 0 : wsum[wid - 1];
    int run = warp_excl + (v - local);   // exclusive prefix for this thread
    for (int i = beg; i < end; i++) { g_offsets[i] = run; run += g_count[i]; }
    if (t == SCAN_T - 1) g_offsets[N] = run;
}

__global__ void reorder_kernel(const void* __restrict__ ei, int E) {
    int e = blockIdx.x * blockDim.x + threadIdx.x;
    if (e >= E) return;
    int s, d;
    load_edge(ei, e, E, s, d);
    int pos = g_offsets[d] + atomicAdd(&g_cursor[d], 1);
    g_se[pos] = make_int2(s, e);
}

// T[n,m] = dot( gelu( X[n,:] @ W_A^T ), W_B[m,:] )
__global__ void compute_T_kernel(const float* __restrict__ X,
                                 const float* __restrict__ WA,
                                 const float* __restrict__ WB,
                                 int N) {
    __shared__ float xs[16][HIDDEN];
    __shared__ float gs[16][HIDDEN];
    int t = threadIdx.x;
    int base = blockIdx.x * 16;

    #pragma unroll
    for (int r = 0; r < 16; r++) {
        int n = base + r;
        xs[r][t] = (n < N) ? X[(size_t)n * HIDDEN + t] : 0.f;
    }
    __syncthreads();

    const float* wa = WA + (size_t)t * HIDDEN;
    float acc[16];
    #pragma unroll
    for (int r = 0; r < 16; r++) acc[r] = 0.f;
    for (int k = 0; k < HIDDEN; k++) {
        float w = __ldg(wa + k);
        #pragma unroll
        for (int r = 0; r < 16; r++) acc[r] += xs[r][k] * w;
    }
    #pragma unroll
    for (int r = 0; r < 16; r++) gs[r][t] = gelu_exact(acc[r]);
    __syncthreads();

    int r = t >> 3, m = t & 7;
    int n = base + r;
    if (n < N) {
        const float* wb = WB + (size_t)m * HIDDEN;
        float a = 0.f;
        for (int k = 0; k < HIDDEN; k++) a += gs[r][k] * __ldg(wb + k);
        g_T[(size_t)n * MIX + m] = a;
    }
}

// ONE WARP per dst node. Lane l owns h = 4l..4l+3 (float4), all 8 mix accs in regs.
// Per edge per warp: Phase A = 3 LDG + 32 FMA/thread, Phase C = 3 LDG + 1 STG.128.
// No shared memory, no barriers.
#define WPB 8
__global__ void __launch_bounds__(32 * WPB, 4)
fused_kernel(const float* __restrict__ X, float* __restrict__ out, int N) {
    int d = blockIdx.x * WPB + (threadIdx.x >> 5);
    if (d >= N) return;
    int lane = threadIdx.x & 31;

    int beg = g_offsets[d];
    int end = g_offsets[d + 1];
    if (beg == end) return;

    float a0[8], a1[8], a2[8], a3[8];
    #pragma unroll
    for (int m = 0; m < 8; m++) { a0[m] = 0.f; a1[m] = 0.f; a2[m] = 0.f; a3[m] = 0.f; }

    // Phase A: agg[d, 4l..4l+3, m] += X[s, 4l..4l+3] * T[s, m]
    for (int i = beg; i < end; i++) {
        int s = __ldg(&g_se[i].x);
        float4 x = __ldg((const float4*)(X + (size_t)s * HIDDEN) + lane);
        const float4* Tp = (const float4*)(g_T + (size_t)s * MIX);
        float4 t0 = __ldg(Tp);
        float4 t1 = __ldg(Tp + 1);
        float t[8] = {t0.x, t0.y, t0.z, t0.w, t1.x, t1.y, t1.z, t1.w};
        #pragma unroll
        for (int m = 0; m < 8; m++) {
            a0[m] = fmaf(x.x, t[m], a0[m]);
            a1[m] = fmaf(x.y, t[m], a1[m]);
            a2[m] = fmaf(x.z, t[m], a2[m]);
            a3[m] = fmaf(x.w, t[m], a3[m]);
        }
    }

    // Phase B: gelu in registers
    #pragma unroll
    for (int m = 0; m < 8; m++) {
        a0[m] = gelu_exact(a0[m]);
        a1[m] = gelu_exact(a1[m]);
        a2[m] = gelu_exact(a2[m]);
        a3[m] = gelu_exact(a3[m]);
    }

    // Phase C: out[e, 4l..4l+3] = sum_m agg[d, 4l..4l+3, m] * T[s_e, m]
    for (int i = beg; i < end; i++) {
        int2 p = __ldg(&g_se[i]);
        const float4* Tp = (const float4*)(g_T + (size_t)p.x * MIX);
        float4 t0 = __ldg(Tp);
        float4 t1 = __ldg(Tp + 1);
        float t[8] = {t0.x, t0.y, t0.z, t0.w, t1.x, t1.y, t1.z, t1.w};
        float4 r = make_float4(0.f, 0.f, 0.f, 0.f);
        #pragma unroll
        for (int m = 0; m < 8; m++) {
            r.x = fmaf(a0[m], t[m], r.x);
            r.y = fmaf(a1[m], t[m], r.y);
            r.z = fmaf(a2[m], t[m], r.z);
            r.w = fmaf(a3[m], t[m], r.w);
        }
        *(float4*)(out + (size_t)p.y * HIDDEN + 4 * lane) = r;
    }
}

// Optional tail: src/dst appended as floats (full-tuple output case)
__global__ void tail_kernel(const void* __restrict__ ei, float* __restrict__ out, int E) {
    int e = blockIdx.x * blockDim.x + threadIdx.x;
    if (e >= E) return;
    int s, d;
    load_edge(ei, e, E, s, d);
    out[(size_t)E * HIDDEN + e] = (float)s;
    out[(size_t)E * HIDDEN + E + e] = (float)d;
}

extern "C" void kernel_launch(void* const* d_in, const int* in_sizes, int n_in,
                              void* d_out, int out_size) {
    const float* X  = (const float*)d_in[0];
    const float* WA = (const float*)d_in[1];
    const float* WB = (const float*)d_in[2];
    const void*  ei = d_in[3];

    int N = in_sizes[0] / HIDDEN;   // 10000
    int E = in_sizes[3] / 2;        // 320000
    float* out = (float*)d_out;

    // Host-side stream/event handles (created once; host objects only, no device mem).
    static cudaStream_t s_side = nullptr;
    static cudaEvent_t ev_fork = nullptr, ev_T = nullptr, ev_join = nullptr;
    if (s_side == nullptr) {
        cudaStreamCreateWithFlags(&s_side, cudaStreamNonBlocking);
        cudaEventCreateWithFlags(&ev_fork, cudaEventDisableTiming);
        cudaEventCreateWithFlags(&ev_T, cudaEventDisableTiming);
        cudaEventCreateWithFlags(&ev_join, cudaEventDisableTiming);
    }

    bool want_tail = ((long long)out_size >= (long long)E * (HIDDEN + 2));

    // Main stream (0): prep -> hist -> scan -> reorder -> [wait T] -> fused -> [join]
    // Side stream:     [wait fork] compute_T -> (ev_T) -> tail? -> (ev_join)
    prep_kernel<<<(N + 255) / 256, 256>>>((const unsigned int*)ei, N);
    cudaEventRecord(ev_fork, 0);
    cudaStreamWaitEvent(s_side, ev_fork, 0);

    compute_T_kernel<<<(N + 15) / 16, 128, 0, s_side>>>(X, WA, WB, N);
    cudaEventRecord(ev_T, s_side);
    if (want_tail) {
        tail_kernel<<<(E + 255) / 256, 256, 0, s_side>>>(ei, out, E);
    }
    cudaEventRecord(ev_join, s_side);

    hist_kernel<<<(E + 255) / 256, 256>>>(ei, E);
    scan_kernel<<<1, SCAN_T>>>(N);
    reorder_kernel<<<(E + 255) / 256, 256>>>(ei, E);

    cudaStreamWaitEvent(0, ev_T, 0);
    fused_kernel<<<(N + WPB - 1) / WPB, 32 * WPB>>>(X, out, N);
    cudaStreamWaitEvent(0, ev_join, 0);
}

// round 7
// speedup vs baseline: 1.6809x; 1.0362x over previous
#include <cuda_runtime.h>
#include <math.h>

#define HIDDEN 128
#define MIX 8
#define MAXN 10000
#define MAXE 512000

// Scratch (allocation-free rule: __device__ globals)
__device__ __align__(16) float g_T[MAXN * MIX];      // per-node hyper weights
__device__ int g_count[MAXN];
__device__ int g_cursor[MAXN];
__device__ int g_offsets[MAXN + 1];
__device__ __align__(8) int2 g_se[MAXE];             // sorted (src, edge_id)
__device__ int g_is64;

__device__ __forceinline__ float gelu_exact(float x) {
    return 0.5f * x * (1.0f + erff(x * 0.70710678118654752f));
}

__device__ __forceinline__ void load_edge(const void* ei, int e, int E, int& s, int& d) {
    if (g_is64) {
        const long long* p = (const long long*)ei;
        s = (int)p[e];
        d = (int)p[(size_t)E + e];
    } else {
        const int* p = (const int*)ei;
        s = p[e];
        d = p[(size_t)E + e];
    }
}

// Zero counters + detect int64-vs-int32 edge_index (node ids < N => int64 high words 0)
__global__ void prep_kernel(const unsigned int* __restrict__ w, int N) {
    int i = blockIdx.x * blockDim.x + threadIdx.x;
    if (i < N) { g_count[i] = 0; g_cursor[i] = 0; }
    if (i == 0) {
        int is64 = 1;
        #pragma unroll
        for (int k = 0; k < 64; k++)
            if (w[2 * k + 1] != 0u) is64 = 0;
        g_is64 = is64;
    }
}

__global__ void hist_kernel(const void* __restrict__ ei, int E) {
    int e = blockIdx.x * blockDim.x + threadIdx.x;
    if (e >= E) return;
    int s, d;
    load_edge(ei, e, E, s, d);
    atomicAdd(&g_count[d], 1);
}

#define SCAN_T 1024
__global__ void scan_kernel(int N) {
    __shared__ int wsum[32];
    int t = threadIdx.x;
    int lane = t & 31, wid = t >> 5;
    int per = (N + SCAN_T - 1) / SCAN_T;
    int beg = t * per;
    int end = min(beg + per, N);

    int local = 0;
    for (int i = beg; i < end; i++) local += g_count[i];

    int v = local;
    #pragma unroll
    for (int off = 1; off < 32; off <<= 1) {
        int u = __shfl_up_sync(0xffffffffu, v, off);
        if (lane >= off) v += u;
    }
    if (lane == 31) wsum[wid] = v;
    __syncthreads();
    if (wid == 0) {
        int wv = wsum[lane];
        #pragma unroll
        for (int off = 1; off < 32; off <<= 1) {
            int u = __shfl_up_sync(0xffffffffu, wv, off);
            if (lane >= off) wv += u;
        }
        wsum[lane] = wv;
    }
    __syncthreads();

    int warp_excl = (wid == 0) ? 0 : wsum[wid - 1];
    int run = warp_excl + (v - local);   // exclusive prefix for this thread
    for (int i = beg; i < end; i++) { g_offsets[i] = run; run += g_count[i]; }
    if (t == SCAN_T - 1) g_offsets[N] = run;
}

__global__ void reorder_kernel(const void* __restrict__ ei, int E) {
    int e = blockIdx.x * blockDim.x + threadIdx.x;
    if (e >= E) return;
    int s, d;
    load_edge(ei, e, E, s, d);
    int pos = g_offsets[d] + atomicAdd(&g_cursor[d], 1);
    g_se[pos] = make_int2(s, e);
}

// T[n,m] = dot( gelu( X[n,:] @ W_A^T ), W_B[m,:] )
__global__ void compute_T_kernel(const float* __restrict__ X,
                                 const float* __restrict__ WA,
                                 const float* __restrict__ WB,
                                 int N) {
    __shared__ float xs[16][HIDDEN];
    __shared__ float gs[16][HIDDEN];
    int t = threadIdx.x;
    int base = blockIdx.x * 16;

    #pragma unroll
    for (int r = 0; r < 16; r++) {
        int n = base + r;
        xs[r][t] = (n < N) ? X[(size_t)n * HIDDEN + t] : 0.f;
    }
    __syncthreads();

    const float* wa = WA + (size_t)t * HIDDEN;
    float acc[16];
    #pragma unroll
    for (int r = 0; r < 16; r++) acc[r] = 0.f;
    for (int k = 0; k < HIDDEN; k++) {
        float w = __ldg(wa + k);
        #pragma unroll
        for (int r = 0; r < 16; r++) acc[r] += xs[r][k] * w;
    }
    #pragma unroll
    for (int r = 0; r < 16; r++) gs[r][t] = gelu_exact(acc[r]);
    __syncthreads();

    int r = t >> 3, m = t & 7;
    int n = base + r;
    if (n < N) {
        const float* wb = WB + (size_t)m * HIDDEN;
        float a = 0.f;
        for (int k = 0; k < HIDDEN; k++) a += gs[r][k] * __ldg(wb + k);
        g_T[(size_t)n * MIX + m] = a;
    }
}

// ONE WARP per dst node. Lane l owns h = 4l..4l+3, all 8 mix accs in regs.
// Both per-edge loops UNROLLED x2: both edges' operands (se, X.128, 2x T.128)
// issue before any FMA -> MLP=2 within an iteration, halving exposed L2 latency.
#define WPB 4
__global__ void __launch_bounds__(32 * WPB)
fused_kernel(const float* __restrict__ X, float* __restrict__ out, int N) {
    int d = blockIdx.x * WPB + (threadIdx.x >> 5);
    if (d >= N) return;
    int lane = threadIdx.x & 31;

    int beg = g_offsets[d];
    int end = g_offsets[d + 1];
    if (beg == end) return;

    float a0[8], a1[8], a2[8], a3[8];
    #pragma unroll
    for (int m = 0; m < 8; m++) { a0[m] = 0.f; a1[m] = 0.f; a2[m] = 0.f; a3[m] = 0.f; }

    // Phase A: agg[d, 4l..4l+3, m] += X[s, 4l..4l+3] * T[s, m]   (unroll x2)
    int i = beg;
    for (; i + 2 <= end; i += 2) {
        int s0 = __ldg(&g_se[i].x);
        int s1 = __ldg(&g_se[i + 1].x);
        float4 x0 = __ldg((const float4*)(X + (size_t)s0 * HIDDEN) + lane);
        float4 x1 = __ldg((const float4*)(X + (size_t)s1 * HIDDEN) + lane);
        const float4* Tp0 = (const float4*)(g_T + (size_t)s0 * MIX);
        const float4* Tp1 = (const float4*)(g_T + (size_t)s1 * MIX);
        float4 ta0 = __ldg(Tp0), ta1 = __ldg(Tp0 + 1);
        float4 tb0 = __ldg(Tp1), tb1 = __ldg(Tp1 + 1);
        float ta[8] = {ta0.x, ta0.y, ta0.z, ta0.w, ta1.x, ta1.y, ta1.z, ta1.w};
        float tb[8] = {tb0.x, tb0.y, tb0.z, tb0.w, tb1.x, tb1.y, tb1.z, tb1.w};
        #pragma unroll
        for (int m = 0; m < 8; m++) {
            a0[m] = fmaf(x0.x, ta[m], a0[m]);
            a1[m] = fmaf(x0.y, ta[m], a1[m]);
            a2[m] = fmaf(x0.z, ta[m], a2[m]);
            a3[m] = fmaf(x0.w, ta[m], a3[m]);
        }
        #pragma unroll
        for (int m = 0; m < 8; m++) {
            a0[m] = fmaf(x1.x, tb[m], a0[m]);
            a1[m] = fmaf(x1.y, tb[m], a1[m]);
            a2[m] = fmaf(x1.z, tb[m], a2[m]);
            a3[m] = fmaf(x1.w, tb[m], a3[m]);
        }
    }
    if (i < end) {
        int s = __ldg(&g_se[i].x);
        float4 x = __ldg((const float4*)(X + (size_t)s * HIDDEN) + lane);
        const float4* Tp = (const float4*)(g_T + (size_t)s * MIX);
        float4 t0 = __ldg(Tp), t1 = __ldg(Tp + 1);
        float t[8] = {t0.x, t0.y, t0.z, t0.w, t1.x, t1.y, t1.z, t1.w};
        #pragma unroll
        for (int m = 0; m < 8; m++) {
            a0[m] = fmaf(x.x, t[m], a0[m]);
            a1[m] = fmaf(x.y, t[m], a1[m]);
            a2[m] = fmaf(x.z, t[m], a2[m]);
            a3[m] = fmaf(x.w, t[m], a3[m]);
        }
    }

    // Phase B: gelu in registers
    #pragma unroll
    for (int m = 0; m < 8; m++) {
        a0[m] = gelu_exact(a0[m]);
        a1[m] = gelu_exact(a1[m]);
        a2[m] = gelu_exact(a2[m]);
        a3[m] = gelu_exact(a3[m]);
    }

    // Phase C: out[e, 4l..4l+3] = sum_m agg[d, 4l..4l+3, m] * T[s_e, m]   (unroll x2)
    i = beg;
    for (; i + 2 <= end; i += 2) {
        int2 p0 = __ldg(&g_se[i]);
        int2 p1 = __ldg(&g_se[i + 1]);
        const float4* Tp0 = (const float4*)(g_T + (size_t)p0.x * MIX);
        const float4* Tp1 = (const float4*)(g_T + (size_t)p1.x * MIX);
        float4 ta0 = __ldg(Tp0), ta1 = __ldg(Tp0 + 1);
        float4 tb0 = __ldg(Tp1), tb1 = __ldg(Tp1 + 1);
        float ta[8] = {ta0.x, ta0.y, ta0.z, ta0.w, ta1.x, ta1.y, ta1.z, ta1.w};
        float tb[8] = {tb0.x, tb0.y, tb0.z, tb0.w, tb1.x, tb1.y, tb1.z, tb1.w};
        float4 r0 = make_float4(0.f, 0.f, 0.f, 0.f);
        float4 r1 = make_float4(0.f, 0.f, 0.f, 0.f);
        #pragma unroll
        for (int m = 0; m < 8; m++) {
            r0.x = fmaf(a0[m], ta[m], r0.x);
            r0.y = fmaf(a1[m], ta[m], r0.y);
            r0.z = fmaf(a2[m], ta[m], r0.z);
            r0.w = fmaf(a3[m], ta[m], r0.w);
            r1.x = fmaf(a0[m], tb[m], r1.x);
            r1.y = fmaf(a1[m], tb[m], r1.y);
            r1.z = fmaf(a2[m], tb[m], r1.z);
            r1.w = fmaf(a3[m], tb[m], r1.w);
        }
        *(float4*)(out + (size_t)p0.y * HIDDEN + 4 * lane) = r0;
        *(float4*)(out + (size_t)p1.y * HIDDEN + 4 * lane) = r1;
    }
    if (i < end) {
        int2 p = __ldg(&g_se[i]);
        const float4* Tp = (const float4*)(g_T + (size_t)p.x * MIX);
        float4 t0 = __ldg(Tp), t1 = __ldg(Tp + 1);
        float t[8] = {t0.x, t0.y, t0.z, t0.w, t1.x, t1.y, t1.z, t1.w};
        float4 r = make_float4(0.f, 0.f, 0.f, 0.f);
        #pragma unroll
        for (int m = 0; m < 8; m++) {
            r.x = fmaf(a0[m], t[m], r.x);
            r.y = fmaf(a1[m], t[m], r.y);
            r.z = fmaf(a2[m], t[m], r.z);
            r.w = fmaf(a3[m], t[m], r.w);
        }
        *(float4*)(out + (size_t)p.y * HIDDEN + 4 * lane) = r;
    }
}

// Optional tail: src/dst appended as floats (full-tuple output case)
__global__ void tail_kernel(const void* __restrict__ ei, float* __restrict__ out, int E) {
    int e = blockIdx.x * blockDim.x + threadIdx.x;
    if (e >= E) return;
    int s, d;
    load_edge(ei, e, E, s, d);
    out[(size_t)E * HIDDEN + e] = (float)s;
    out[(size_t)E * HIDDEN + E + e] = (float)d;
}

extern "C" void kernel_launch(void* const* d_in, const int* in_sizes, int n_in,
                              void* d_out, int out_size) {
    const float* X  = (const float*)d_in[0];
    const float* WA = (const float*)d_in[1];
    const float* WB = (const float*)d_in[2];
    const void*  ei = d_in[3];

    int N = in_sizes[0] / HIDDEN;   // 10000
    int E = in_sizes[3] / 2;        // 320000
    float* out = (float*)d_out;

    // Host-side stream/event handles (created once; host objects only, no device mem).
    static cudaStream_t s_side = nullptr;
    static cudaEvent_t ev_fork = nullptr, ev_T = nullptr, ev_join = nullptr;
    if (s_side == nullptr) {
        cudaStreamCreateWithFlags(&s_side, cudaStreamNonBlocking);
        cudaEventCreateWithFlags(&ev_fork, cudaEventDisableTiming);
        cudaEventCreateWithFlags(&ev_T, cudaEventDisableTiming);
        cudaEventCreateWithFlags(&ev_join, cudaEventDisableTiming);
    }

    bool want_tail = ((long long)out_size >= (long long)E * (HIDDEN + 2));

    // Main stream (0): prep -> hist -> scan -> reorder -> [wait T] -> fused -> [join]
    // Side stream:     [wait fork] compute_T -> (ev_T) -> tail? -> (ev_join)
    prep_kernel<<<(N + 255) / 256, 256>>>((const unsigned int*)ei, N);
    cudaEventRecord(ev_fork, 0);
    cudaStreamWaitEvent(s_side, ev_fork, 0);

    compute_T_kernel<<<(N + 15) / 16, 128, 0, s_side>>>(X, WA, WB, N);
    cudaEventRecord(ev_T, s_side);
    if (want_tail) {
        tail_kernel<<<(E + 255) / 256, 256, 0, s_side>>>(ei, out, E);
    }
    cudaEventRecord(ev_join, s_side);

    hist_kernel<<<(E + 255) / 256, 256>>>(ei, E);
    scan_kernel<<<1, SCAN_T>>>(N);
    reorder_kernel<<<(E + 255) / 256, 256>>>(ei, E);

    cudaStreamWaitEvent(0, ev_T, 0);
    fused_kernel<<<(N + WPB - 1) / WPB, 32 * WPB>>>(X, out, N);
    cudaStreamWaitEvent(0, ev_join, 0);
}

// round 8
// speedup vs baseline: 1.7150x; 1.0203x over previous
#include <cuda_runtime.h>
#include <math.h>

#define HIDDEN 128
#define MIX 8
#define MAXN 10000
#define MAXE 512000

// Scratch (allocation-free rule: __device__ globals)
__device__ __align__(16) float g_T[MAXN * MIX];      // per-node hyper weights
__device__ int g_count[MAXN];
__device__ int g_cursor[MAXN];
__device__ int g_offsets[MAXN + 1];
__device__ __align__(8) int2 g_se[MAXE];             // sorted (src, edge_id)
__device__ int g_is64;

__device__ __forceinline__ float gelu_exact(float x) {
    return 0.5f * x * (1.0f + erff(x * 0.70710678118654752f));
}

__device__ __forceinline__ void load_edge(const void* ei, int e, int E, int& s, int& d) {
    if (g_is64) {
        const long long* p = (const long long*)ei;
        s = (int)p[e];
        d = (int)p[(size_t)E + e];
    } else {
        const int* p = (const int*)ei;
        s = p[e];
        d = p[(size_t)E + e];
    }
}

// Zero counters + detect int64-vs-int32 edge_index (node ids < N => int64 high words 0)
__global__ void prep_kernel(const unsigned int* __restrict__ w, int N) {
    int i = blockIdx.x * blockDim.x + threadIdx.x;
    if (i < N) { g_count[i] = 0; g_cursor[i] = 0; }
    if (i == 0) {
        int is64 = 1;
        #pragma unroll
        for (int k = 0; k < 64; k++)
            if (w[2 * k + 1] != 0u) is64 = 0;
        g_is64 = is64;
    }
}

__global__ void hist_kernel(const void* __restrict__ ei, int E) {
    int e = blockIdx.x * blockDim.x + threadIdx.x;
    if (e >= E) return;
    int s, d;
    load_edge(ei, e, E, s, d);
    atomicAdd(&g_count[d], 1);
}

#define SCAN_T 1024
__global__ void scan_kernel(int N) {
    __shared__ int wsum[32];
    int t = threadIdx.x;
    int lane = t & 31, wid = t >> 5;
    int per = (N + SCAN_T - 1) / SCAN_T;
    int beg = t * per;
    int end = min(beg + per, N);

    int local = 0;
    for (int i = beg; i < end; i++) local += g_count[i];

    int v = local;
    #pragma unroll
    for (int off = 1; off < 32; off <<= 1) {
        int u = __shfl_up_sync(0xffffffffu, v, off);
        if (lane >= off) v += u;
    }
    if (lane == 31) wsum[wid] = v;
    __syncthreads();
    if (wid == 0) {
        int wv = wsum[lane];
        #pragma unroll
        for (int off = 1; off < 32; off <<= 1) {
            int u = __shfl_up_sync(0xffffffffu, wv, off);
            if (lane >= off) wv += u;
        }
        wsum[lane] = wv;
    }
    __syncthreads();

    int warp_excl = (wid == 0) ? 0 : wsum[wid - 1];
    int run = warp_excl + (v - local);   // exclusive prefix for this thread
    for (int i = beg; i < end; i++) { g_offsets[i] = run; run += g_count[i]; }
    if (t == SCAN_T - 1) g_offsets[N] = run;
}

__global__ void reorder_kernel(const void* __restrict__ ei, int E) {
    int e = blockIdx.x * blockDim.x + threadIdx.x;
    if (e >= E) return;
    int s, d;
    load_edge(ei, e, E, s, d);
    int pos = g_offsets[d] + atomicAdd(&g_cursor[d], 1);
    g_se[pos] = make_int2(s, e);
}

// T[n,m] = dot( gelu( X[n,:] @ W_A^T ), W_B[m,:] )
__global__ void compute_T_kernel(const float* __restrict__ X,
                                 const float* __restrict__ WA,
                                 const float* __restrict__ WB,
                                 int N) {
    __shared__ float xs[16][HIDDEN];
    __shared__ float gs[16][HIDDEN];
    int t = threadIdx.x;
    int base = blockIdx.x * 16;

    #pragma unroll
    for (int r = 0; r < 16; r++) {
        int n = base + r;
        xs[r][t] = (n < N) ? X[(size_t)n * HIDDEN + t] : 0.f;
    }
    __syncthreads();

    const float* wa = WA + (size_t)t * HIDDEN;
    float acc[16];
    #pragma unroll
    for (int r = 0; r < 16; r++) acc[r] = 0.f;
    for (int k = 0; k < HIDDEN; k++) {
        float w = __ldg(wa + k);
        #pragma unroll
        for (int r = 0; r < 16; r++) acc[r] += xs[r][k] * w;
    }
    #pragma unroll
    for (int r = 0; r < 16; r++) gs[r][t] = gelu_exact(acc[r]);
    __syncthreads();

    int r = t >> 3, m = t & 7;
    int n = base + r;
    if (n < N) {
        const float* wb = WB + (size_t)m * HIDDEN;
        float a = 0.f;
        for (int k = 0; k < HIDDEN; k++) a += gs[r][k] * __ldg(wb + k);
        g_T[(size_t)n * MIX + m] = a;
    }
}

// ONE WARP per dst node. Lane l owns h = 4l..4l+3, all 8 mix accs in regs.
// SOFTWARE-PIPELINED: edge i+1's (se, X.128, 2x T.128) loads issue BEFORE edge i's
// FMAs, so next-iteration memory latency hides under current FMA work.
// __launch_bounds__(128, 4) pins regs <= 128 -> >= 16 warps/SM.
#define WPB 4
__global__ void __launch_bounds__(32 * WPB, 4)
fused_kernel(const float* __restrict__ X, float* __restrict__ out, int N) {
    int d = blockIdx.x * WPB + (threadIdx.x >> 5);
    if (d >= N) return;
    int lane = threadIdx.x & 31;

    int beg = g_offsets[d];
    int end = g_offsets[d + 1];
    if (beg == end) return;

    float a0[8], a1[8], a2[8], a3[8];
    #pragma unroll
    for (int m = 0; m < 8; m++) { a0[m] = 0.f; a1[m] = 0.f; a2[m] = 0.f; a3[m] = 0.f; }

    // ---- Phase A (pipelined): agg[d, 4l..4l+3, m] += X[s, 4l..4l+3] * T[s, m] ----
    {
        int sc = __ldg(&g_se[beg].x);
        float4 xc = __ldg((const float4*)(X + (size_t)sc * HIDDEN) + lane);
        const float4* Tc = (const float4*)(g_T + (size_t)sc * MIX);
        float4 tc0 = __ldg(Tc), tc1 = __ldg(Tc + 1);

        for (int i = beg; i < end - 1; i++) {
            int sn = __ldg(&g_se[i + 1].x);
            float4 xn = __ldg((const float4*)(X + (size_t)sn * HIDDEN) + lane);
            const float4* Tn = (const float4*)(g_T + (size_t)sn * MIX);
            float4 tn0 = __ldg(Tn), tn1 = __ldg(Tn + 1);

            float t[8] = {tc0.x, tc0.y, tc0.z, tc0.w, tc1.x, tc1.y, tc1.z, tc1.w};
            #pragma unroll
            for (int m = 0; m < 8; m++) {
                a0[m] = fmaf(xc.x, t[m], a0[m]);
                a1[m] = fmaf(xc.y, t[m], a1[m]);
                a2[m] = fmaf(xc.z, t[m], a2[m]);
                a3[m] = fmaf(xc.w, t[m], a3[m]);
            }
            xc = xn; tc0 = tn0; tc1 = tn1;
        }
        float t[8] = {tc0.x, tc0.y, tc0.z, tc0.w, tc1.x, tc1.y, tc1.z, tc1.w};
        #pragma unroll
        for (int m = 0; m < 8; m++) {
            a0[m] = fmaf(xc.x, t[m], a0[m]);
            a1[m] = fmaf(xc.y, t[m], a1[m]);
            a2[m] = fmaf(xc.z, t[m], a2[m]);
            a3[m] = fmaf(xc.w, t[m], a3[m]);
        }
    }

    // ---- Phase B: gelu in registers ----
    #pragma unroll
    for (int m = 0; m < 8; m++) {
        a0[m] = gelu_exact(a0[m]);
        a1[m] = gelu_exact(a1[m]);
        a2[m] = gelu_exact(a2[m]);
        a3[m] = gelu_exact(a3[m]);
    }

    // ---- Phase C (pipelined): out[e, 4l..4l+3] = sum_m agg * T[s_e, m] ----
    {
        int2 pc = __ldg(&g_se[beg]);
        const float4* Tc = (const float4*)(g_T + (size_t)pc.x * MIX);
        float4 tc0 = __ldg(Tc), tc1 = __ldg(Tc + 1);

        for (int i = beg; i < end - 1; i++) {
            int2 pn = __ldg(&g_se[i + 1]);
            const float4* Tn = (const float4*)(g_T + (size_t)pn.x * MIX);
            float4 tn0 = __ldg(Tn), tn1 = __ldg(Tn + 1);

            float t[8] = {tc0.x, tc0.y, tc0.z, tc0.w, tc1.x, tc1.y, tc1.z, tc1.w};
            float4 r = make_float4(0.f, 0.f, 0.f, 0.f);
            #pragma unroll
            for (int m = 0; m < 8; m++) {
                r.x = fmaf(a0[m], t[m], r.x);
                r.y = fmaf(a1[m], t[m], r.y);
                r.z = fmaf(a2[m], t[m], r.z);
                r.w = fmaf(a3[m], t[m], r.w);
            }
            *(float4*)(out + (size_t)pc.y * HIDDEN + 4 * lane) = r;
            pc = pn; tc0 = tn0; tc1 = tn1;
        }
        float t[8] = {tc0.x, tc0.y, tc0.z, tc0.w, tc1.x, tc1.y, tc1.z, tc1.w};
        float4 r = make_float4(0.f, 0.f, 0.f, 0.f);
        #pragma unroll
        for (int m = 0; m < 8; m++) {
            r.x = fmaf(a0[m], t[m], r.x);
            r.y = fmaf(a1[m], t[m], r.y);
            r.z = fmaf(a2[m], t[m], r.z);
            r.w = fmaf(a3[m], t[m], r.w);
        }
        *(float4*)(out + (size_t)pc.y * HIDDEN + 4 * lane) = r;
    }
}

// Optional tail: src/dst appended as floats (full-tuple output case)
__global__ void tail_kernel(const void* __restrict__ ei, float* __restrict__ out, int E) {
    int e = blockIdx.x * blockDim.x + threadIdx.x;
    if (e >= E) return;
    int s, d;
    load_edge(ei, e, E, s, d);
    out[(size_t)E * HIDDEN + e] = (float)s;
    out[(size_t)E * HIDDEN + E + e] = (float)d;
}

extern "C" void kernel_launch(void* const* d_in, const int* in_sizes, int n_in,
                              void* d_out, int out_size) {
    const float* X  = (const float*)d_in[0];
    const float* WA = (const float*)d_in[1];
    const float* WB = (const float*)d_in[2];
    const void*  ei = d_in[3];

    int N = in_sizes[0] / HIDDEN;   // 10000
    int E = in_sizes[3] / 2;        // 320000
    float* out = (float*)d_out;

    // Host-side stream/event handles (created once; host objects only, no device mem).
    static cudaStream_t s_side = nullptr;
    static cudaEvent_t ev_fork = nullptr, ev_T = nullptr, ev_r = nullptr, ev_join = nullptr;
    if (s_side == nullptr) {
        cudaStreamCreateWithFlags(&s_side, cudaStreamNonBlocking);
        cudaEventCreateWithFlags(&ev_fork, cudaEventDisableTiming);
        cudaEventCreateWithFlags(&ev_T, cudaEventDisableTiming);
        cudaEventCreateWithFlags(&ev_r, cudaEventDisableTiming);
        cudaEventCreateWithFlags(&ev_join, cudaEventDisableTiming);
    }

    bool want_tail = ((long long)out_size >= (long long)E * (HIDDEN + 2));

    // Main stream (0): prep -> hist -> scan -> reorder -> [wait T] -> fused -> [join]
    // Side stream:     [wait fork] compute_T -> (ev_T) ... [wait reorder] tail -> (ev_join)
    // (tail submitted AFTER fused so fused is the 6th launch -> ncu -s 5 captures it)
    prep_kernel<<<(N + 255) / 256, 256>>>((const unsigned int*)ei, N);
    cudaEventRecord(ev_fork, 0);
    cudaStreamWaitEvent(s_side, ev_fork, 0);

    compute_T_kernel<<<(N + 15) / 16, 128, 0, s_side>>>(X, WA, WB, N);
    cudaEventRecord(ev_T, s_side);

    hist_kernel<<<(E + 255) / 256, 256>>>(ei, E);
    scan_kernel<<<1, SCAN_T>>>(N);
    reorder_kernel<<<(E + 255) / 256, 256>>>(ei, E);
    cudaEventRecord(ev_r, 0);

    cudaStreamWaitEvent(0, ev_T, 0);
    fused_kernel<<<(N + WPB - 1) / WPB, 32 * WPB>>>(X, out, N);

    if (want_tail) {
        cudaStreamWaitEvent(s_side, ev_r, 0);
        tail_kernel<<<(E + 255) / 256, 256, 0, s_side>>>(ei, out, E);
        cudaEventRecord(ev_join, s_side);
        cudaStreamWaitEvent(0, ev_join, 0);
    }
}